// round 9
// baseline (speedup 1.0000x reference)
#include <cuda_runtime.h>
#include <cuda_fp16.h>
#include <mma.h>
#include <cstdint>

using namespace nvcuda;

#define N_NODES 100000
#define N_EDGES 1600000

// ---------------------------------------------------------------------------
// Device scratch
// ---------------------------------------------------------------------------
__device__ float4 g_msg[(size_t)N_NODES * 32];   // 51.2 MB
__device__ __half g_whi[5 * 128 * 128];          // W^T split planes [chunk][n][k]
__device__ __half g_wlo[5 * 128 * 128];
__device__ int    g_mode;
__device__ int    g_cnt[N_NODES];                // degree histogram
__device__ int    g_off[N_NODES + 1];            // CSR offsets
__device__ int    g_cur[N_NODES];                // fill cursors
__device__ int    g_eid[N_EDGES];                // edge ids grouped by dst

// ---------------------------------------------------------------------------
// dst index fetch (mode: 0=int32, 1=int64, 2=float32)
// ---------------------------------------------------------------------------
__device__ __forceinline__ int get_dst(const void* eiv, int mode, int i) {
    int d;
    if (mode == 1)      d = (int)((const long long*)eiv)[N_EDGES + i];
    else if (mode == 0) d = ((const int*)eiv)[N_EDGES + i];
    else                d = (int)((const float*)eiv)[N_EDGES + i];
    return min(max(d, 0), N_NODES - 1);
}

// ---------------------------------------------------------------------------
// init: zero histogram; block 0 thread 0 also detects edge_index dtype
// ---------------------------------------------------------------------------
__global__ void init_kernel(const void* eiv) {
    int i = blockIdx.x * blockDim.x + threadIdx.x;
    if (i < N_NODES) g_cnt[i] = 0;
    if (i == 0) {
        const long long* e64 = (const long long*)eiv;
        const int*       e32 = (const int*)eiv;
        const float*     ef  = (const float*)eiv;
        bool ok64 = true, ok32 = true, okf = true;
        for (int k = 0; k < 32; k++) {
            long long v = e64[k];
            if (v < 0 || v >= N_NODES) ok64 = false;
            int w = e32[k];
            if (w < 0 || w >= N_NODES) ok32 = false;
            float f = ef[k];
            if (!(f >= 0.f && f < (float)N_NODES)) okf = false;
        }
        g_mode = ok64 ? 1 : (ok32 ? 0 : (okf ? 2 : 0));
    }
}

// ---------------------------------------------------------------------------
// histogram of destination nodes
// ---------------------------------------------------------------------------
__global__ void hist_kernel(const void* __restrict__ eiv) {
    __shared__ int mode;
    if (threadIdx.x == 0) mode = g_mode;
    __syncthreads();
    int i = blockIdx.x * blockDim.x + threadIdx.x;
    if (i >= N_EDGES) return;
    atomicAdd(&g_cnt[get_dst(eiv, mode, i)], 1);
}

// ---------------------------------------------------------------------------
// exclusive scan over 100000 counters (single block, 1024 threads)
// ---------------------------------------------------------------------------
__global__ void scan_kernel() {
    __shared__ int ps[1024];
    const int t = threadIdx.x;
    const int CH = (N_NODES + 1023) / 1024;           // 98
    const int s0 = t * CH;
    const int s1 = min(s0 + CH, N_NODES);
    int sum = 0;
    for (int i = s0; i < s1; i++) sum += g_cnt[i];
    ps[t] = sum;
    __syncthreads();
    #pragma unroll
    for (int off = 1; off < 1024; off <<= 1) {
        int v = (t >= off) ? ps[t - off] : 0;
        __syncthreads();
        ps[t] += v;
        __syncthreads();
    }
    int base = ps[t] - sum;                           // exclusive prefix
    for (int i = s0; i < s1; i++) {
        int c = g_cnt[i];
        g_off[i] = base;
        g_cur[i] = base;
        base += c;
    }
    if (t == 1023) g_off[N_NODES] = base;
}

// ---------------------------------------------------------------------------
// fill CSR edge-id list
// ---------------------------------------------------------------------------
__global__ void fill_kernel(const void* __restrict__ eiv) {
    __shared__ int mode;
    if (threadIdx.x == 0) mode = g_mode;
    __syncthreads();
    int i = blockIdx.x * blockDim.x + threadIdx.x;
    if (i >= N_EDGES) return;
    int d = get_dst(eiv, mode, i);
    int pos = atomicAdd(&g_cur[d], 1);
    g_eid[pos] = i;
}

// ---------------------------------------------------------------------------
// gather: one warp per node, lane handles 16 B of the 512 B edge row.
// No atomics; writes every node (degree-0 rows become zeros).
// ---------------------------------------------------------------------------
__global__ void gather_kernel(const float4* __restrict__ e4,
                              float4* __restrict__ msg) {
    int node = (blockIdx.x * blockDim.x + threadIdx.x) >> 5;
    int lane = threadIdx.x & 31;
    if (node >= N_NODES) return;
    int s = g_off[node];
    int e = g_off[node + 1];
    float4 acc = make_float4(0.f, 0.f, 0.f, 0.f);
    for (int base = s; base < e; base += 32) {
        int n = min(32, e - base);
        int myeid = (base + lane < e) ? g_eid[base + lane] : 0;
        for (int i = 0; i < n; i++) {
            int eid = __shfl_sync(0xFFFFFFFFu, myeid, i);
            float4 v = e4[(size_t)eid * 32 + lane];
            acc.x += v.x; acc.y += v.y; acc.z += v.z; acc.w += v.w;
        }
    }
    msg[(size_t)node * 32 + lane] = acc;
}

// ---------------------------------------------------------------------------
// weight prep: transpose to [n][k], split into fp16 hi/lo (hi+lo ~ exact W)
// chunk 0,1 = W0 (k 0-127 / 128-255); 2,3 = Wh[0],Wh[1]; 4 = Wo
// ---------------------------------------------------------------------------
__global__ void prep_kernel(const float* __restrict__ W0,
                            const float* __restrict__ Wh,
                            const float* __restrict__ Wo) {
    int i = blockIdx.x * 256 + threadIdx.x;
    if (i >= 5 * 128 * 128) return;
    int chunk = i >> 14;
    int r = i & 16383;
    int n = r >> 7, k = r & 127;
    float v;
    if (chunk < 2)      v = W0[(chunk * 128 + k) * 128 + n];
    else if (chunk < 4) v = Wh[(chunk - 2) * 16384 + k * 128 + n];
    else                v = Wo[k * 128 + n];
    __half h = __float2half_rn(v);
    __half l = __float2half_rn(v - __half2float(h));
    g_whi[i] = h;
    g_wlo[i] = l;
}

// ---------------------------------------------------------------------------
// Fused 4-layer MLP: one CTA per 128-row tile, 512 threads, 16 warps (4x4).
// Activations: single fp16 plane. Weights: fp16 hi/lo planes (split = exact).
// C = A*Whi + A*Wlo  -> 2 HMMA products per k-step.
// ---------------------------------------------------------------------------
#define SSTR 136
#define SB   (SSTR * 2)                 // 272 B per plane row
#define SA   0
#define SWH  (128 * SB)                 // 34816
#define SWL  (2 * 128 * SB)             // 69632
#define SRED (3 * 128 * SB)             // 104448
#define SMEM_T (SRED + 2048 + 64)       // 106560
#define CSTR 132                        // fp32 C row stride

__device__ __forceinline__ void stage_w(char* smem,
                                        const __half* __restrict__ Whi_g,
                                        const __half* __restrict__ Wlo_g,
                                        int chunk, int tid) {
    const uint4* wh = (const uint4*)(Whi_g + chunk * 16384);
    const uint4* wl = (const uint4*)(Wlo_g + chunk * 16384);
    #pragma unroll
    for (int it = 0; it < 4; it++) {
        int i = tid + it * 512;          // 2048 x 16B per plane
        int n = i >> 4, c16 = i & 15;
        uint32_t dst = n * SB + c16 * 16;
        *(uint4*)(smem + SWH + dst) = wh[i];
        *(uint4*)(smem + SWL + dst) = wl[i];
    }
}

__device__ __forceinline__ void mma_tile(
    wmma::fragment<wmma::accumulator, 16, 16, 16, float> (&acc)[2][2],
    const char* smem, int wy, int wx) {
    const __half* Ah = (const __half*)(smem + SA);
    const __half* Wh = (const __half*)(smem + SWH);
    const __half* Wl = (const __half*)(smem + SWL);
    #pragma unroll 1
    for (int ks = 0; ks < 8; ks++) {
        const int k0 = ks * 16;
        wmma::fragment<wmma::matrix_a, 16, 16, 16, __half, wmma::row_major> af[2];
        wmma::fragment<wmma::matrix_b, 16, 16, 16, __half, wmma::col_major> bh[2], bl[2];
        #pragma unroll
        for (int i = 0; i < 2; i++)
            wmma::load_matrix_sync(af[i], &Ah[(wy * 32 + i * 16) * SSTR + k0], SSTR);
        #pragma unroll
        for (int j = 0; j < 2; j++)
            wmma::load_matrix_sync(bh[j], &Wh[(wx * 32 + j * 16) * SSTR + k0], SSTR);
        #pragma unroll
        for (int i = 0; i < 2; i++)
            #pragma unroll
            for (int j = 0; j < 2; j++)
                wmma::mma_sync(acc[i][j], af[i], bh[j], acc[i][j]);
        #pragma unroll
        for (int j = 0; j < 2; j++)
            wmma::load_matrix_sync(bl[j], &Wl[(wx * 32 + j * 16) * SSTR + k0], SSTR);
        #pragma unroll
        for (int i = 0; i < 2; i++)
            #pragma unroll
            for (int j = 0; j < 2; j++)
                wmma::mma_sync(acc[i][j], af[i], bl[j], acc[i][j]);
    }
}

__device__ __forceinline__ void zero_acc(
    wmma::fragment<wmma::accumulator, 16, 16, 16, float> (&acc)[2][2]) {
    #pragma unroll
    for (int i = 0; i < 2; i++)
        #pragma unroll
        for (int j = 0; j < 2; j++) wmma::fill_fragment(acc[i][j], 0.f);
}

__device__ __forceinline__ void spill_acc(
    wmma::fragment<wmma::accumulator, 16, 16, 16, float> (&acc)[2][2],
    char* smem, int wy, int wx) {
    float* Cs = (float*)(smem + SA);
    #pragma unroll
    for (int i = 0; i < 2; i++)
        #pragma unroll
        for (int j = 0; j < 2; j++)
            wmma::store_matrix_sync(&Cs[(wy * 32 + i * 16) * CSTR + wx * 32 + j * 16],
                                    acc[i][j], CSTR, wmma::mem_row_major);
}

// thread handles row=tid>>2, cols quad*32..+31 (quad = tid&3): 32 values
__device__ __forceinline__ void load_v(const char* smem, const float* __restrict__ bias,
                                       int row, int quad, bool relu, float (&v)[32]) {
    const float* Cs = (const float*)(smem + SA);
    #pragma unroll
    for (int q = 0; q < 8; q++) {
        float4 cc = *(const float4*)&Cs[row * CSTR + quad * 32 + q * 4];
        float4 bb = __ldg((const float4*)bias + quad * 8 + q);
        v[q * 4 + 0] = cc.x + bb.x;
        v[q * 4 + 1] = cc.y + bb.y;
        v[q * 4 + 2] = cc.z + bb.z;
        v[q * 4 + 3] = cc.w + bb.w;
    }
    if (relu) {
        #pragma unroll
        for (int j = 0; j < 32; j++) v[j] = fmaxf(v[j], 0.f);
    }
}

// write 32 fp16 activations (64 B = 4 uint4) into the A plane
__device__ __forceinline__ void store_a(char* smem, int row, int quad,
                                        const float (&v)[32]) {
    #pragma unroll
    for (int g = 0; g < 4; g++) {
        uint4 p;
        uint32_t* pu = (uint32_t*)&p;
        #pragma unroll
        for (int q = 0; q < 4; q++) {
            __half2 h2 = __floats2half2_rn(v[g * 8 + q * 2], v[g * 8 + q * 2 + 1]);
            pu[q] = *(uint32_t*)&h2;
        }
        *(uint4*)(smem + SA + row * SB + quad * 64 + g * 16) = p;
    }
}

__global__ void __launch_bounds__(512, 1)
fused_mlp_kernel(const float* __restrict__ x, const float* __restrict__ msgf,
                 const __half* __restrict__ Whi_g, const __half* __restrict__ Wlo_g,
                 const float* __restrict__ b0, const float* __restrict__ bh,
                 const float* __restrict__ bo,
                 const float* __restrict__ gw, const float* __restrict__ gb,
                 float* __restrict__ outf, int nrows) {
    extern __shared__ char smem[];
    const int tid = threadIdx.x, wid = tid >> 5;
    const int row0 = blockIdx.x * 128;
    const int wy = wid >> 2, wx = wid & 3;     // 4x4 warp grid, 32x32 each
    const int row  = tid >> 2;                 // epilogue row (0..127)
    const int quad = tid & 3;                  // column quarter
    const int rg   = row0 + row;
    const bool valid = rg < nrows;

    wmma::fragment<wmma::accumulator, 16, 16, 16, float> acc[2][2];
    float v[32];

    // ================= layer 0: relu([x | msg] @ W0 + b0) =================
    zero_acc(acc);
    #pragma unroll
    for (int c = 0; c < 2; c++) {
        stage_w(smem, Whi_g, Wlo_g, c, tid);
        const float4* src = (const float4*)(c == 0 ? x : msgf);
        #pragma unroll
        for (int it = 0; it < 8; it++) {
            int i = tid + it * 512;            // 4096 float4
            int r = i >> 5, c4 = i & 31;
            int rr = row0 + r; if (rr >= nrows) rr = nrows - 1;
            float4 w = src[(size_t)rr * 32 + c4];
            __half2 h0 = __floats2half2_rn(w.x, w.y);
            __half2 h1 = __floats2half2_rn(w.z, w.w);
            uint2 p;
            p.x = *(uint32_t*)&h0;
            p.y = *(uint32_t*)&h1;
            *(uint2*)(smem + SA + r * SB + c4 * 8) = p;
        }
        __syncthreads();
        mma_tile(acc, smem, wy, wx);
        __syncthreads();
    }
    spill_acc(acc, smem, wy, wx);
    __syncthreads();
    load_v(smem, b0, row, quad, true, v);
    __syncthreads();
    store_a(smem, row, quad, v);
    stage_w(smem, Whi_g, Wlo_g, 2, tid);       // next layer's W
    __syncthreads();

    // ================= hidden layers 1,2 =================
    #pragma unroll
    for (int layer = 0; layer < 2; layer++) {
        zero_acc(acc);
        mma_tile(acc, smem, wy, wx);
        __syncthreads();
        spill_acc(acc, smem, wy, wx);
        __syncthreads();
        load_v(smem, bh + layer * 128, row, quad, true, v);
        __syncthreads();
        store_a(smem, row, quad, v);
        stage_w(smem, Whi_g, Wlo_g, 3 + layer, tid);
        __syncthreads();
    }

    // ================= output layer + GroupNorm + residual =================
    zero_acc(acc);
    mma_tile(acc, smem, wy, wx);
    __syncthreads();
    spill_acc(acc, smem, wy, wx);
    __syncthreads();
    load_v(smem, bo, row, quad, false, v);

    float s = 0.f, ss = 0.f;
    #pragma unroll
    for (int j = 0; j < 32; j++) { s += v[j]; ss += v[j] * v[j]; }
    s  += __shfl_xor_sync(0xFFFFFFFFu, s,  1);
    ss += __shfl_xor_sync(0xFFFFFFFFu, ss, 1);
    s  += __shfl_xor_sync(0xFFFFFFFFu, s,  2);
    ss += __shfl_xor_sync(0xFFFFFFFFu, ss, 2);
    float mu  = s * (1.f / 128.f);
    float var = ss * (1.f / 128.f) - mu * mu;
    float rs  = rsqrtf(var + 1e-5f);
    if (valid) {
        const float4* x4  = (const float4*)x;
        const float4* gw4 = (const float4*)gw;
        const float4* gb4 = (const float4*)gb;
        float4* o4 = (float4*)outf;
        #pragma unroll
        for (int q = 0; q < 8; q++) {
            float4 xg = x4[(size_t)rg * 32 + quad * 8 + q];
            float4 wv = __ldg(gw4 + quad * 8 + q);
            float4 bv = __ldg(gb4 + quad * 8 + q);
            float4 r4;
            r4.x = xg.x + (v[q * 4 + 0] - mu) * rs * wv.x + bv.x;
            r4.y = xg.y + (v[q * 4 + 1] - mu) * rs * wv.y + bv.y;
            r4.z = xg.z + (v[q * 4 + 2] - mu) * rs * wv.z + bv.z;
            r4.w = xg.w + (v[q * 4 + 3] - mu) * rs * wv.w + bv.w;
            o4[(size_t)rg * 32 + quad * 8 + q] = r4;
        }
    }
}

// ---------------------------------------------------------------------------
// launch
// ---------------------------------------------------------------------------
extern "C" void kernel_launch(void* const* d_in, const int* in_sizes, int n_in,
                              void* d_out, int out_size) {
    const float* x  = (const float*)d_in[0];
    const float* e  = (const float*)d_in[1];
    const void*  ei = d_in[2];
    const float* W0 = (const float*)d_in[3];
    const float* b0 = (const float*)d_in[4];
    const float* Wh = (const float*)d_in[5];
    const float* bh = (const float*)d_in[6];
    const float* Wo = (const float*)d_in[7];
    const float* bo = (const float*)d_in[8];
    const float* gw = (const float*)d_in[9];
    const float* gb = (const float*)d_in[10];
    float* out = (float*)d_out;

    float4* msg;
    __half *whi, *wlo;
    cudaGetSymbolAddress((void**)&msg, g_msg);
    cudaGetSymbolAddress((void**)&whi, g_whi);
    cudaGetSymbolAddress((void**)&wlo, g_wlo);

    cudaFuncSetAttribute(fused_mlp_kernel, cudaFuncAttributeMaxDynamicSharedMemorySize, SMEM_T);

    // CSR build + gather (replaces zero + atomic scatter)
    init_kernel<<<(N_NODES + 1023) / 1024, 1024>>>(ei);
    hist_kernel<<<(N_EDGES + 1023) / 1024, 1024>>>(ei);
    scan_kernel<<<1, 1024>>>();
    fill_kernel<<<(N_EDGES + 1023) / 1024, 1024>>>(ei);
    gather_kernel<<<(N_NODES * 32 + 255) / 256, 256>>>((const float4*)e, msg);

    prep_kernel<<<(5 * 128 * 128 + 255) / 256, 256>>>(W0, Wh, Wo);

    const int gblocks = (N_NODES + 127) / 128;   // 782
    fused_mlp_kernel<<<gblocks, 512, SMEM_T>>>(
        x, (const float*)msg, whi, wlo, b0, bh, bo, gw, gb, out, N_NODES);
}

// round 10
// speedup vs baseline: 1.0217x; 1.0217x over previous
#include <cuda_runtime.h>
#include <cuda_fp16.h>
#include <mma.h>
#include <cstdint>

using namespace nvcuda;

#define N_NODES 100000
#define N_EDGES 1600000

// ---------------------------------------------------------------------------
// Device scratch
// ---------------------------------------------------------------------------
__device__ float4 g_msg[(size_t)N_NODES * 32];   // 51.2 MB
__device__ __half g_whi[5 * 128 * 128];          // W^T split planes [chunk][n][k]
__device__ __half g_wlo[5 * 128 * 128];
__device__ int    g_mode;

// ---------------------------------------------------------------------------
// detect edge_index dtype (reads only first 32 src entries)
// ---------------------------------------------------------------------------
__global__ void detect_kernel(const void* eiv) {
    if (threadIdx.x != 0 || blockIdx.x != 0) return;
    const long long* e64 = (const long long*)eiv;
    const int*       e32 = (const int*)eiv;
    const float*     ef  = (const float*)eiv;
    bool ok64 = true, ok32 = true, okf = true;
    for (int i = 0; i < 32; i++) {
        long long v = e64[i];
        if (v < 0 || v >= N_NODES) ok64 = false;
        int w = e32[i];
        if (w < 0 || w >= N_NODES) ok32 = false;
        float f = ef[i];
        if (!(f >= 0.f && f < (float)N_NODES)) okf = false;
    }
    g_mode = ok64 ? 1 : (ok32 ? 0 : (okf ? 2 : 0));
}

__global__ void zero_kernel(float4* __restrict__ p, int n4) {
    int i = blockIdx.x * blockDim.x + threadIdx.x;
    if (i < n4) p[i] = make_float4(0.f, 0.f, 0.f, 0.f);
}

// ---------------------------------------------------------------------------
// scatter-sum: each warp handles 4 consecutive edges; lane covers 16 B of the
// 512 B edge row; vector RED into L2-resident msg.
// ---------------------------------------------------------------------------
__global__ void scatter_kernel(const float4* __restrict__ e4,
                               const void* __restrict__ eiv,
                               float4* __restrict__ msg) {
    __shared__ int mode;
    if (threadIdx.x == 0) mode = g_mode;
    __syncthreads();
    int warp = (blockIdx.x * blockDim.x + threadIdx.x) >> 5;
    int lane = threadIdx.x & 31;
    int e0 = warp * 4;
    if (e0 >= N_EDGES) return;
    #pragma unroll
    for (int k = 0; k < 4; k++) {
        int e = e0 + k;
        if (e >= N_EDGES) break;
        int d;
        if (mode == 1)      d = (int)((const long long*)eiv)[N_EDGES + e];
        else if (mode == 0) d = ((const int*)eiv)[N_EDGES + e];
        else                d = (int)((const float*)eiv)[N_EDGES + e];
        d = min(max(d, 0), N_NODES - 1);
        float4 v = e4[(size_t)e * 32 + lane];
        float4* p = &msg[(size_t)d * 32 + lane];
        asm volatile("red.global.add.v4.f32 [%0], {%1,%2,%3,%4};"
                     :: "l"(p), "f"(v.x), "f"(v.y), "f"(v.z), "f"(v.w) : "memory");
    }
}

// ---------------------------------------------------------------------------
// weight prep: transpose to [n][k], split into fp16 hi/lo (hi+lo ~ exact W)
// chunk 0,1 = W0 (k 0-127 / 128-255); 2,3 = Wh[0],Wh[1]; 4 = Wo
// ---------------------------------------------------------------------------
__global__ void prep_kernel(const float* __restrict__ W0,
                            const float* __restrict__ Wh,
                            const float* __restrict__ Wo) {
    int i = blockIdx.x * 256 + threadIdx.x;
    if (i >= 5 * 128 * 128) return;
    int chunk = i >> 14;
    int r = i & 16383;
    int n = r >> 7, k = r & 127;
    float v;
    if (chunk < 2)      v = W0[(chunk * 128 + k) * 128 + n];
    else if (chunk < 4) v = Wh[(chunk - 2) * 16384 + k * 128 + n];
    else                v = Wo[k * 128 + n];
    __half h = __float2half_rn(v);
    __half l = __float2half_rn(v - __half2float(h));
    g_whi[i] = h;
    g_wlo[i] = l;
}

// ---------------------------------------------------------------------------
// Fused 4-layer MLP: 64-row tiles, 256 threads, 2 CTAs/SM for phase overlap.
// 8 warps in 2x4 grid, each owns 32x32 (acc 2x2 frags).
// Activations: single fp16 plane. Weights: fp16 hi/lo planes (exact split).
// C = A*Whi + A*Wlo -> 2 HMMA products per k-step.
// smem: A(64x272B) | Whi(128x272B) | Wlo(128x272B). C spill (fp32, stride 132,
// 33792 B) aliases A + front of Whi (both dead at spill time).
// ---------------------------------------------------------------------------
#define SSTR 136
#define SB   (SSTR * 2)                 // 272 B per plane row
#define SA   0
#define SWH  (64 * SB)                  // 17408
#define SWL  (SWH + 128 * SB)           // 52224
#define SMEM_T (SWL + 128 * SB + 64)    // 87104
#define CSTR 132                        // fp32 C row stride (64*132*4 = 33792)

__device__ __forceinline__ void stage_w(char* smem,
                                        const __half* __restrict__ Whi_g,
                                        const __half* __restrict__ Wlo_g,
                                        int chunk, int tid) {
    const uint4* wh = (const uint4*)(Whi_g + chunk * 16384);
    const uint4* wl = (const uint4*)(Wlo_g + chunk * 16384);
    #pragma unroll
    for (int it = 0; it < 8; it++) {
        int i = tid + it * 256;          // 2048 x 16B per plane
        int n = i >> 4, c16 = i & 15;
        uint32_t dst = n * SB + c16 * 16;
        *(uint4*)(smem + SWH + dst) = wh[i];
        *(uint4*)(smem + SWL + dst) = wl[i];
    }
}

__device__ __forceinline__ void mma_tile(
    wmma::fragment<wmma::accumulator, 16, 16, 16, float> (&acc)[2][2],
    const char* smem, int wy, int wx) {
    const __half* Ah = (const __half*)(smem + SA);
    const __half* Wh = (const __half*)(smem + SWH);
    const __half* Wl = (const __half*)(smem + SWL);
    #pragma unroll 1
    for (int ks = 0; ks < 8; ks++) {
        const int k0 = ks * 16;
        wmma::fragment<wmma::matrix_a, 16, 16, 16, __half, wmma::row_major> af[2];
        wmma::fragment<wmma::matrix_b, 16, 16, 16, __half, wmma::col_major> bh[2], bl[2];
        #pragma unroll
        for (int i = 0; i < 2; i++)
            wmma::load_matrix_sync(af[i], &Ah[(wy * 32 + i * 16) * SSTR + k0], SSTR);
        #pragma unroll
        for (int j = 0; j < 2; j++)
            wmma::load_matrix_sync(bh[j], &Wh[(wx * 32 + j * 16) * SSTR + k0], SSTR);
        #pragma unroll
        for (int i = 0; i < 2; i++)
            #pragma unroll
            for (int j = 0; j < 2; j++)
                wmma::mma_sync(acc[i][j], af[i], bh[j], acc[i][j]);
        #pragma unroll
        for (int j = 0; j < 2; j++)
            wmma::load_matrix_sync(bl[j], &Wl[(wx * 32 + j * 16) * SSTR + k0], SSTR);
        #pragma unroll
        for (int i = 0; i < 2; i++)
            #pragma unroll
            for (int j = 0; j < 2; j++)
                wmma::mma_sync(acc[i][j], af[i], bl[j], acc[i][j]);
    }
}

__device__ __forceinline__ void zero_acc(
    wmma::fragment<wmma::accumulator, 16, 16, 16, float> (&acc)[2][2]) {
    #pragma unroll
    for (int i = 0; i < 2; i++)
        #pragma unroll
        for (int j = 0; j < 2; j++) wmma::fill_fragment(acc[i][j], 0.f);
}

__device__ __forceinline__ void spill_acc(
    wmma::fragment<wmma::accumulator, 16, 16, 16, float> (&acc)[2][2],
    char* smem, int wy, int wx) {
    float* Cs = (float*)(smem + SA);
    #pragma unroll
    for (int i = 0; i < 2; i++)
        #pragma unroll
        for (int j = 0; j < 2; j++)
            wmma::store_matrix_sync(&Cs[(wy * 32 + i * 16) * CSTR + wx * 32 + j * 16],
                                    acc[i][j], CSTR, wmma::mem_row_major);
}

// thread handles row=tid>>2 (0..63), cols quad*32..+31 (quad=tid&3)
__device__ __forceinline__ void load_v(const char* smem, const float* __restrict__ bias,
                                       int row, int quad, bool relu, float (&v)[32]) {
    const float* Cs = (const float*)(smem + SA);
    #pragma unroll
    for (int q = 0; q < 8; q++) {
        float4 cc = *(const float4*)&Cs[row * CSTR + quad * 32 + q * 4];
        float4 bb = __ldg((const float4*)bias + quad * 8 + q);
        v[q * 4 + 0] = cc.x + bb.x;
        v[q * 4 + 1] = cc.y + bb.y;
        v[q * 4 + 2] = cc.z + bb.z;
        v[q * 4 + 3] = cc.w + bb.w;
    }
    if (relu) {
        #pragma unroll
        for (int j = 0; j < 32; j++) v[j] = fmaxf(v[j], 0.f);
    }
}

// write 32 fp16 activations (64 B = 4 uint4) into the A plane
__device__ __forceinline__ void store_a(char* smem, int row, int quad,
                                        const float (&v)[32]) {
    #pragma unroll
    for (int g = 0; g < 4; g++) {
        uint4 p;
        uint32_t* pu = (uint32_t*)&p;
        #pragma unroll
        for (int q = 0; q < 4; q++) {
            __half2 h2 = __floats2half2_rn(v[g * 8 + q * 2], v[g * 8 + q * 2 + 1]);
            pu[q] = *(uint32_t*)&h2;
        }
        *(uint4*)(smem + SA + row * SB + quad * 64 + g * 16) = p;
    }
}

__global__ void __launch_bounds__(256, 2)
fused_mlp_kernel(const float* __restrict__ x, const float* __restrict__ msgf,
                 const __half* __restrict__ Whi_g, const __half* __restrict__ Wlo_g,
                 const float* __restrict__ b0, const float* __restrict__ bh,
                 const float* __restrict__ bo,
                 const float* __restrict__ gw, const float* __restrict__ gb,
                 float* __restrict__ outf, int nrows) {
    extern __shared__ char smem[];
    const int tid = threadIdx.x, wid = tid >> 5;
    const int row0 = blockIdx.x * 64;
    const int wy = wid >> 2, wx = wid & 3;     // 2x4 warp grid, 32x32 each
    const int row  = tid >> 2;                 // epilogue row (0..63)
    const int quad = tid & 3;                  // column quarter
    const int rg   = row0 + row;
    const bool valid = rg < nrows;

    wmma::fragment<wmma::accumulator, 16, 16, 16, float> acc[2][2];
    float v[32];

    // ================= layer 0: relu([x | msg] @ W0 + b0) =================
    zero_acc(acc);
    #pragma unroll
    for (int c = 0; c < 2; c++) {
        stage_w(smem, Whi_g, Wlo_g, c, tid);
        const float4* src = (const float4*)(c == 0 ? x : msgf);
        #pragma unroll
        for (int it = 0; it < 8; it++) {
            int i = tid + it * 256;            // 2048 float4
            int r = i >> 5, c4 = i & 31;
            int rr = row0 + r; if (rr >= nrows) rr = nrows - 1;
            float4 w = src[(size_t)rr * 32 + c4];
            __half2 h0 = __floats2half2_rn(w.x, w.y);
            __half2 h1 = __floats2half2_rn(w.z, w.w);
            uint2 p;
            p.x = *(uint32_t*)&h0;
            p.y = *(uint32_t*)&h1;
            *(uint2*)(smem + SA + r * SB + c4 * 8) = p;
        }
        __syncthreads();
        mma_tile(acc, smem, wy, wx);
        __syncthreads();
    }
    spill_acc(acc, smem, wy, wx);
    __syncthreads();
    load_v(smem, b0, row, quad, true, v);
    __syncthreads();
    store_a(smem, row, quad, v);
    stage_w(smem, Whi_g, Wlo_g, 2, tid);       // next layer's W
    __syncthreads();

    // ================= hidden layers 1,2 =================
    #pragma unroll
    for (int layer = 0; layer < 2; layer++) {
        zero_acc(acc);
        mma_tile(acc, smem, wy, wx);
        __syncthreads();
        spill_acc(acc, smem, wy, wx);
        __syncthreads();
        load_v(smem, bh + layer * 128, row, quad, true, v);
        __syncthreads();
        store_a(smem, row, quad, v);
        stage_w(smem, Whi_g, Wlo_g, 3 + layer, tid);
        __syncthreads();
    }

    // ================= output layer + GroupNorm + residual =================
    zero_acc(acc);
    mma_tile(acc, smem, wy, wx);
    __syncthreads();
    spill_acc(acc, smem, wy, wx);
    __syncthreads();
    load_v(smem, bo, row, quad, false, v);

    float s = 0.f, ss = 0.f;
    #pragma unroll
    for (int j = 0; j < 32; j++) { s += v[j]; ss += v[j] * v[j]; }
    s  += __shfl_xor_sync(0xFFFFFFFFu, s,  1);
    ss += __shfl_xor_sync(0xFFFFFFFFu, ss, 1);
    s  += __shfl_xor_sync(0xFFFFFFFFu, s,  2);
    ss += __shfl_xor_sync(0xFFFFFFFFu, ss, 2);
    float mu  = s * (1.f / 128.f);
    float var = ss * (1.f / 128.f) - mu * mu;
    float rs  = rsqrtf(var + 1e-5f);
    if (valid) {
        const float4* x4  = (const float4*)x;
        const float4* gw4 = (const float4*)gw;
        const float4* gb4 = (const float4*)gb;
        float4* o4 = (float4*)outf;
        #pragma unroll
        for (int q = 0; q < 8; q++) {
            float4 xg = x4[(size_t)rg * 32 + quad * 8 + q];
            float4 wv = __ldg(gw4 + quad * 8 + q);
            float4 bv = __ldg(gb4 + quad * 8 + q);
            float4 r4;
            r4.x = xg.x + (v[q * 4 + 0] - mu) * rs * wv.x + bv.x;
            r4.y = xg.y + (v[q * 4 + 1] - mu) * rs * wv.y + bv.y;
            r4.z = xg.z + (v[q * 4 + 2] - mu) * rs * wv.z + bv.z;
            r4.w = xg.w + (v[q * 4 + 3] - mu) * rs * wv.w + bv.w;
            o4[(size_t)rg * 32 + quad * 8 + q] = r4;
        }
    }
}

// ---------------------------------------------------------------------------
// launch
// ---------------------------------------------------------------------------
extern "C" void kernel_launch(void* const* d_in, const int* in_sizes, int n_in,
                              void* d_out, int out_size) {
    const float* x  = (const float*)d_in[0];
    const float* e  = (const float*)d_in[1];
    const void*  ei = d_in[2];
    const float* W0 = (const float*)d_in[3];
    const float* b0 = (const float*)d_in[4];
    const float* Wh = (const float*)d_in[5];
    const float* bh = (const float*)d_in[6];
    const float* Wo = (const float*)d_in[7];
    const float* bo = (const float*)d_in[8];
    const float* gw = (const float*)d_in[9];
    const float* gb = (const float*)d_in[10];
    float* out = (float*)d_out;

    float4* msg;
    __half *whi, *wlo;
    cudaGetSymbolAddress((void**)&msg, g_msg);
    cudaGetSymbolAddress((void**)&whi, g_whi);
    cudaGetSymbolAddress((void**)&wlo, g_wlo);

    cudaFuncSetAttribute(fused_mlp_kernel, cudaFuncAttributeMaxDynamicSharedMemorySize, SMEM_T);

    detect_kernel<<<1, 32>>>(ei);
    zero_kernel<<<(N_NODES * 32 + 255) / 256, 256>>>(msg, N_NODES * 32);
    scatter_kernel<<<(N_EDGES / 4 + 7) / 8, 256>>>((const float4*)e, ei, msg);
    prep_kernel<<<(5 * 128 * 128 + 255) / 256, 256>>>(W0, Wh, Wo);

    const int gblocks = (N_NODES + 63) / 64;     // 1563
    fused_mlp_kernel<<<gblocks, 256, SMEM_T>>>(
        x, (const float*)msg, whi, wlo, b0, bh, bo, gw, gb, out, N_NODES);
}

// round 11
// speedup vs baseline: 1.4204x; 1.3902x over previous
#include <cuda_runtime.h>
#include <cuda_fp16.h>
#include <mma.h>
#include <cstdint>

using namespace nvcuda;

#define N_NODES 100000
#define N_EDGES 1600000

// ---------------------------------------------------------------------------
// Device scratch
// ---------------------------------------------------------------------------
__device__ float4 g_msg[(size_t)N_NODES * 32];   // 51.2 MB
__device__ __half g_w[5 * 128 * 128];            // W^T fp16 planes [chunk][n][k]
__device__ int    g_mode;

// ---------------------------------------------------------------------------
// detect edge_index dtype (reads only first 32 src entries)
// ---------------------------------------------------------------------------
__global__ void detect_kernel(const void* eiv) {
    if (threadIdx.x != 0 || blockIdx.x != 0) return;
    const long long* e64 = (const long long*)eiv;
    const int*       e32 = (const int*)eiv;
    const float*     ef  = (const float*)eiv;
    bool ok64 = true, ok32 = true, okf = true;
    for (int i = 0; i < 32; i++) {
        long long v = e64[i];
        if (v < 0 || v >= N_NODES) ok64 = false;
        int w = e32[i];
        if (w < 0 || w >= N_NODES) ok32 = false;
        float f = ef[i];
        if (!(f >= 0.f && f < (float)N_NODES)) okf = false;
    }
    g_mode = ok64 ? 1 : (ok32 ? 0 : (okf ? 2 : 0));
}

__global__ void zero_kernel(float4* __restrict__ p, int n4) {
    int i = blockIdx.x * blockDim.x + threadIdx.x;
    if (i < n4) p[i] = make_float4(0.f, 0.f, 0.f, 0.f);
}

// ---------------------------------------------------------------------------
// scatter-sum: one warp per edge, lane handles 16 B of the 512 B edge row,
// vector RED into the L2-resident msg buffer. (R8 configuration — best so far.)
// ---------------------------------------------------------------------------
__global__ void scatter_kernel(const float4* __restrict__ e4,
                               const void* __restrict__ eiv,
                               float4* __restrict__ msg) {
    __shared__ int mode;
    if (threadIdx.x == 0) mode = g_mode;
    __syncthreads();
    int warp = (blockIdx.x * blockDim.x + threadIdx.x) >> 5;
    int lane = threadIdx.x & 31;
    if (warp >= N_EDGES) return;
    int d;
    if (mode == 1)      d = (int)((const long long*)eiv)[N_EDGES + warp];
    else if (mode == 0) d = ((const int*)eiv)[N_EDGES + warp];
    else                d = (int)((const float*)eiv)[N_EDGES + warp];
    d = min(max(d, 0), N_NODES - 1);
    float4 v = e4[(size_t)warp * 32 + lane];
    float4* p = &msg[(size_t)d * 32 + lane];
    asm volatile("red.global.add.v4.f32 [%0], {%1,%2,%3,%4};"
                 :: "l"(p), "f"(v.x), "f"(v.y), "f"(v.z), "f"(v.w) : "memory");
}

// ---------------------------------------------------------------------------
// weight prep: transpose to [n][k], round to fp16
// chunk 0,1 = W0 (k 0-127 / 128-255); 2,3 = Wh[0],Wh[1]; 4 = Wo
// ---------------------------------------------------------------------------
__global__ void prep_kernel(const float* __restrict__ W0,
                            const float* __restrict__ Wh,
                            const float* __restrict__ Wo) {
    int i = blockIdx.x * 256 + threadIdx.x;
    if (i >= 5 * 128 * 128) return;
    int chunk = i >> 14;
    int r = i & 16383;
    int n = r >> 7, k = r & 127;
    float v;
    if (chunk < 2)      v = W0[(chunk * 128 + k) * 128 + n];
    else if (chunk < 4) v = Wh[(chunk - 2) * 16384 + k * 128 + n];
    else                v = Wo[k * 128 + n];
    g_w[i] = __float2half_rn(v);
}

// ---------------------------------------------------------------------------
// Fused 4-layer MLP (R8 structure): one CTA per 128-row tile, 512 threads,
// 16 warps in 4x4 grid (32x32 tile each). Single fp16 product per k-step:
// C = A_fp16 * W_fp16, fp32 accumulate.
// smem: A(128x272B) | W(128x272B). C spill (fp32, stride 132, 67584 B)
// aliases A + front of W (both dead at spill time; W restaged after).
// ---------------------------------------------------------------------------
#define SSTR 136
#define SB   (SSTR * 2)                 // 272 B per plane row
#define SA   0
#define SW   (128 * SB)                 // 34816
#define SMEM_T (2 * 128 * SB + 64)      // 69696
#define CSTR 132                        // fp32 C row stride (128*132*4 = 67584)

__device__ __forceinline__ void stage_w(char* smem,
                                        const __half* __restrict__ W_g,
                                        int chunk, int tid) {
    const uint4* w = (const uint4*)(W_g + chunk * 16384);
    #pragma unroll
    for (int it = 0; it < 4; it++) {
        int i = tid + it * 512;          // 2048 x 16B
        int n = i >> 4, c16 = i & 15;
        *(uint4*)(smem + SW + n * SB + c16 * 16) = w[i];
    }
}

__device__ __forceinline__ void mma_tile(
    wmma::fragment<wmma::accumulator, 16, 16, 16, float> (&acc)[2][2],
    const char* smem, int wy, int wx) {
    const __half* Ah = (const __half*)(smem + SA);
    const __half* Wh = (const __half*)(smem + SW);
    #pragma unroll 1
    for (int ks = 0; ks < 8; ks++) {
        const int k0 = ks * 16;
        wmma::fragment<wmma::matrix_a, 16, 16, 16, __half, wmma::row_major> af[2];
        wmma::fragment<wmma::matrix_b, 16, 16, 16, __half, wmma::col_major> bf[2];
        #pragma unroll
        for (int i = 0; i < 2; i++)
            wmma::load_matrix_sync(af[i], &Ah[(wy * 32 + i * 16) * SSTR + k0], SSTR);
        #pragma unroll
        for (int j = 0; j < 2; j++)
            wmma::load_matrix_sync(bf[j], &Wh[(wx * 32 + j * 16) * SSTR + k0], SSTR);
        #pragma unroll
        for (int i = 0; i < 2; i++)
            #pragma unroll
            for (int j = 0; j < 2; j++)
                wmma::mma_sync(acc[i][j], af[i], bf[j], acc[i][j]);
    }
}

__device__ __forceinline__ void zero_acc(
    wmma::fragment<wmma::accumulator, 16, 16, 16, float> (&acc)[2][2]) {
    #pragma unroll
    for (int i = 0; i < 2; i++)
        #pragma unroll
        for (int j = 0; j < 2; j++) wmma::fill_fragment(acc[i][j], 0.f);
}

__device__ __forceinline__ void spill_acc(
    wmma::fragment<wmma::accumulator, 16, 16, 16, float> (&acc)[2][2],
    char* smem, int wy, int wx) {
    float* Cs = (float*)(smem + SA);
    #pragma unroll
    for (int i = 0; i < 2; i++)
        #pragma unroll
        for (int j = 0; j < 2; j++)
            wmma::store_matrix_sync(&Cs[(wy * 32 + i * 16) * CSTR + wx * 32 + j * 16],
                                    acc[i][j], CSTR, wmma::mem_row_major);
}

// thread handles row=tid>>2 (0..127), cols quad*32..+31 (quad=tid&3)
__device__ __forceinline__ void load_v(const char* smem, const float* __restrict__ bias,
                                       int row, int quad, bool relu, float (&v)[32]) {
    const float* Cs = (const float*)(smem + SA);
    #pragma unroll
    for (int q = 0; q < 8; q++) {
        float4 cc = *(const float4*)&Cs[row * CSTR + quad * 32 + q * 4];
        float4 bb = __ldg((const float4*)bias + quad * 8 + q);
        v[q * 4 + 0] = cc.x + bb.x;
        v[q * 4 + 1] = cc.y + bb.y;
        v[q * 4 + 2] = cc.z + bb.z;
        v[q * 4 + 3] = cc.w + bb.w;
    }
    if (relu) {
        #pragma unroll
        for (int j = 0; j < 32; j++) v[j] = fmaxf(v[j], 0.f);
    }
}

// write 32 fp16 activations (64 B = 4 uint4) into the A plane
__device__ __forceinline__ void store_a(char* smem, int row, int quad,
                                        const float (&v)[32]) {
    #pragma unroll
    for (int g = 0; g < 4; g++) {
        uint4 p;
        uint32_t* pu = (uint32_t*)&p;
        #pragma unroll
        for (int q = 0; q < 4; q++) {
            __half2 h2 = __floats2half2_rn(v[g * 8 + q * 2], v[g * 8 + q * 2 + 1]);
            pu[q] = *(uint32_t*)&h2;
        }
        *(uint4*)(smem + SA + row * SB + quad * 64 + g * 16) = p;
    }
}

__global__ void __launch_bounds__(512, 1)
fused_mlp_kernel(const float* __restrict__ x, const float* __restrict__ msgf,
                 const __half* __restrict__ W_g,
                 const float* __restrict__ b0, const float* __restrict__ bh,
                 const float* __restrict__ bo,
                 const float* __restrict__ gw, const float* __restrict__ gb,
                 float* __restrict__ outf, int nrows) {
    extern __shared__ char smem[];
    const int tid = threadIdx.x, wid = tid >> 5;
    const int row0 = blockIdx.x * 128;
    const int wy = wid >> 2, wx = wid & 3;     // 4x4 warp grid, 32x32 each
    const int row  = tid >> 2;                 // epilogue row (0..127)
    const int quad = tid & 3;                  // column quarter
    const int rg   = row0 + row;
    const bool valid = rg < nrows;

    wmma::fragment<wmma::accumulator, 16, 16, 16, float> acc[2][2];
    float v[32];

    // ================= layer 0: relu([x | msg] @ W0 + b0) =================
    zero_acc(acc);
    #pragma unroll
    for (int c = 0; c < 2; c++) {
        stage_w(smem, W_g, c, tid);
        const float4* src = (const float4*)(c == 0 ? x : msgf);
        #pragma unroll
        for (int it = 0; it < 8; it++) {
            int i = tid + it * 512;            // 4096 float4
            int r = i >> 5, c4 = i & 31;
            int rr = row0 + r; if (rr >= nrows) rr = nrows - 1;
            float4 w = src[(size_t)rr * 32 + c4];
            __half2 h0 = __floats2half2_rn(w.x, w.y);
            __half2 h1 = __floats2half2_rn(w.z, w.w);
            uint2 p;
            p.x = *(uint32_t*)&h0;
            p.y = *(uint32_t*)&h1;
            *(uint2*)(smem + SA + r * SB + c4 * 8) = p;
        }
        __syncthreads();
        mma_tile(acc, smem, wy, wx);
        __syncthreads();
    }
    spill_acc(acc, smem, wy, wx);
    __syncthreads();
    load_v(smem, b0, row, quad, true, v);
    __syncthreads();
    store_a(smem, row, quad, v);
    stage_w(smem, W_g, 2, tid);                // next layer's W
    __syncthreads();

    // ================= hidden layers 1,2 =================
    #pragma unroll
    for (int layer = 0; layer < 2; layer++) {
        zero_acc(acc);
        mma_tile(acc, smem, wy, wx);
        __syncthreads();
        spill_acc(acc, smem, wy, wx);
        __syncthreads();
        load_v(smem, bh + layer * 128, row, quad, true, v);
        __syncthreads();
        store_a(smem, row, quad, v);
        stage_w(smem, W_g, 3 + layer, tid);
        __syncthreads();
    }

    // ================= output layer + GroupNorm + residual =================
    zero_acc(acc);
    mma_tile(acc, smem, wy, wx);
    __syncthreads();
    spill_acc(acc, smem, wy, wx);
    __syncthreads();
    load_v(smem, bo, row, quad, false, v);

    float s = 0.f, ss = 0.f;
    #pragma unroll
    for (int j = 0; j < 32; j++) { s += v[j]; ss += v[j] * v[j]; }
    s  += __shfl_xor_sync(0xFFFFFFFFu, s,  1);
    ss += __shfl_xor_sync(0xFFFFFFFFu, ss, 1);
    s  += __shfl_xor_sync(0xFFFFFFFFu, s,  2);
    ss += __shfl_xor_sync(0xFFFFFFFFu, ss, 2);
    float mu  = s * (1.f / 128.f);
    float var = ss * (1.f / 128.f) - mu * mu;
    float rs  = rsqrtf(var + 1e-5f);
    if (valid) {
        const float4* x4  = (const float4*)x;
        const float4* gw4 = (const float4*)gw;
        const float4* gb4 = (const float4*)gb;
        float4* o4 = (float4*)outf;
        #pragma unroll
        for (int q = 0; q < 8; q++) {
            float4 xg = x4[(size_t)rg * 32 + quad * 8 + q];
            float4 wv = __ldg(gw4 + quad * 8 + q);
            float4 bv = __ldg(gb4 + quad * 8 + q);
            float4 r4;
            r4.x = xg.x + (v[q * 4 + 0] - mu) * rs * wv.x + bv.x;
            r4.y = xg.y + (v[q * 4 + 1] - mu) * rs * wv.y + bv.y;
            r4.z = xg.z + (v[q * 4 + 2] - mu) * rs * wv.z + bv.z;
            r4.w = xg.w + (v[q * 4 + 3] - mu) * rs * wv.w + bv.w;
            o4[(size_t)rg * 32 + quad * 8 + q] = r4;
        }
    }
}

// ---------------------------------------------------------------------------
// launch
// ---------------------------------------------------------------------------
extern "C" void kernel_launch(void* const* d_in, const int* in_sizes, int n_in,
                              void* d_out, int out_size) {
    const float* x  = (const float*)d_in[0];
    const float* e  = (const float*)d_in[1];
    const void*  ei = d_in[2];
    const float* W0 = (const float*)d_in[3];
    const float* b0 = (const float*)d_in[4];
    const float* Wh = (const float*)d_in[5];
    const float* bh = (const float*)d_in[6];
    const float* Wo = (const float*)d_in[7];
    const float* bo = (const float*)d_in[8];
    const float* gw = (const float*)d_in[9];
    const float* gb = (const float*)d_in[10];
    float* out = (float*)d_out;

    float4* msg;
    __half* w;
    cudaGetSymbolAddress((void**)&msg, g_msg);
    cudaGetSymbolAddress((void**)&w, g_w);

    cudaFuncSetAttribute(fused_mlp_kernel, cudaFuncAttributeMaxDynamicSharedMemorySize, SMEM_T);

    detect_kernel<<<1, 32>>>(ei);
    zero_kernel<<<(N_NODES * 32 + 255) / 256, 256>>>(msg, N_NODES * 32);
    scatter_kernel<<<N_EDGES / 8, 256>>>((const float4*)e, ei, msg);
    prep_kernel<<<(5 * 128 * 128 + 255) / 256, 256>>>(W0, Wh, Wo);

    const int gblocks = (N_NODES + 127) / 128;   // 782
    fused_mlp_kernel<<<gblocks, 512, SMEM_T>>>(
        x, (const float*)msg, w, b0, bh, bo, gw, gb, out, N_NODES);
}